// round 10
// baseline (speedup 1.0000x reference)
#include <cuda_runtime.h>
#include <math.h>

#define H 1024
#define V 50257
#define L 4096
#define NPART 512                   // fused-attn blocks (8 enc rows each)
#define NRED 64                     // reducer blocks inside fused kernel
#define FIN_BLOCKS ((V + 255) / 256)   // 197
#define NEG_BIG (-3.0e38f)

// ---------------- device scratch (no allocations allowed) ----------------
__device__ float g_concat[2 * H];            // [0..H) = ctx, [H..2H) = h_new
__device__ float4 g_ctx_part4[NPART * 256];  // 512 partials x 1024 cols (float4) = 2 MB
__device__ float g_spart[2 * NPART];         // per-block (max, sumexp) for attn softmax
__device__ float g_part[2 * FIN_BLOCKS];     // per-block (max, sumexp) for logit LSE
__device__ int g_syncA, g_syncB, g_syncC;    // fused kernel phases
__device__ int g_lse_done;                   // finalize grid sync

// ---------------- helpers ----------------
__device__ __forceinline__ float warp_sum(float v) {
#pragma unroll
    for (int o = 16; o > 0; o >>= 1) v += __shfl_down_sync(0xFFFFFFFFu, v, o);
    return v;
}
__device__ __forceinline__ float dot4(const float4 a, const float4 b) {
    return a.x * b.x + a.y * b.y + a.z * b.z + a.w * b.w;
}
__device__ __forceinline__ void spin_until(volatile int* c, int n) {
    while (*c < n) { }
}

// ============ 1) FUSED: GRU (2 outputs/block) -> scores -> softmax -> ctx ============
// Low register pressure version: enc rows are NOT cached in registers across phases;
// phase 2 re-reads them from L2 (enc is L2-resident after phase 1).
__global__ void __launch_bounds__(256, 4) fused_attn_kernel(
    const int* __restrict__ inp, const float* __restrict__ hidden,
    const float* __restrict__ embedding,
    const float* __restrict__ w_ih, const float* __restrict__ w_hh,
    const float* __restrict__ b_ih, const float* __restrict__ b_hh,
    const float* __restrict__ enc, float* __restrict__ out_h)
{
    __shared__ float4 sv[H / 4];      // phase0: x(emb); phase1: h_new
    __shared__ float4 hv4[H / 4];     // phase0: hidden
    __shared__ float red[12][8];
    __shared__ float sarr[8];
    __shared__ float wts[8];
    const int tid = threadIdx.x;
    const int warp = tid >> 5, lane = tid & 31;
    const int b = blockIdx.x;

    if (b == 0 && tid == 0) g_lse_done = 0;   // reset finalize counter for this replay

    // ---------------- phase 0: GRU, outputs j0 and j0+1 ----------------
    const int idx = inp[0];
    const int j0 = b * 2;
    const float4* emb4 = (const float4*)(embedding + (size_t)idx * H);
    const float4* hid4 = (const float4*)hidden;
    sv[tid]  = emb4[tid];
    hv4[tid] = hid4[tid];
    __syncthreads();
    {
        const float4 xv = sv[tid];
        const float4 hv = hv4[tid];
        const float4* wi = (const float4*)w_ih;
        const float4* wh = (const float4*)w_hh;
        float a[12];
#pragma unroll
        for (int jj = 0; jj < 2; jj++) {
            const int j = j0 + jj;
#pragma unroll
            for (int g = 0; g < 3; g++) {
                a[jj * 6 + g]     = dot4(wi[(size_t)(j + g * H) * 256 + tid], xv);
                a[jj * 6 + 3 + g] = dot4(wh[(size_t)(j + g * H) * 256 + tid], hv);
            }
        }
#pragma unroll
        for (int q = 0; q < 12; q++) {
            a[q] = warp_sum(a[q]);
            if (lane == 0) red[q][warp] = a[q];
        }
    }
    __syncthreads();
    if (tid < 2) {
        const int j = j0 + tid;
        float s[6];
#pragma unroll
        for (int g = 0; g < 6; g++) {
            float t = red[tid * 6 + g][0];
#pragma unroll
            for (int k = 1; k < 8; k++) t += red[tid * 6 + g][k];
            s[g] = t;
        }
        const float i_r = s[0] + b_ih[j];
        const float i_z = s[1] + b_ih[j + H];
        const float i_n = s[2] + b_ih[j + 2 * H];
        const float h_r = s[3] + b_hh[j];
        const float h_z = s[4] + b_hh[j + H];
        const float h_n = s[5] + b_hh[j + 2 * H];
        const float r = 1.f / (1.f + __expf(-(i_r + h_r)));
        const float z = 1.f / (1.f + __expf(-(i_z + h_z)));
        const float n = tanhf(i_n + r * h_n);
        const float hj = ((const float*)hv4)[j];
        const float val = (1.f - z) * n + z * hj;
        g_concat[H + j] = val;
        out_h[j]        = val;
    }
    __threadfence();
    __syncthreads();
    if (tid == 0) { atomicAdd(&g_syncA, 1); spin_until(&g_syncA, NPART); }
    __syncthreads();
    __threadfence();

    // ---------------- phase 1: scores for rows l0..l0+7 (enc streamed, not cached) ----
    sv[tid] = ((const float4*)g_concat)[256 + tid];   // h_new
    __syncthreads();
    const float4 hsh = sv[tid];
    const int l0 = b * 8;
    const float4* e4 = (const float4*)enc;
    {
        float p[8];
#pragma unroll
        for (int l = 0; l < 8; l++)
            p[l] = dot4(e4[(size_t)(l0 + l) * 256 + tid], hsh);
#pragma unroll
        for (int l = 0; l < 8; l++) {
            p[l] = warp_sum(p[l]);
            if (lane == 0) red[l][warp] = p[l];
        }
    }
    __syncthreads();
    if (tid < 8) {
        float t = red[tid][0];
#pragma unroll
        for (int k = 1; k < 8; k++) t += red[tid][k];
        sarr[tid] = t;
    }
    __syncthreads();
    if (tid == 0) {
        float m = sarr[0];
#pragma unroll
        for (int k = 1; k < 8; k++) m = fmaxf(m, sarr[k]);
        float s = 0.f;
#pragma unroll
        for (int k = 0; k < 8; k++) s += __expf(sarr[k] - m);
        g_spart[2 * b]     = m;
        g_spart[2 * b + 1] = s;
    }
    __threadfence();
    __syncthreads();
    if (tid == 0) { atomicAdd(&g_syncB, 1); spin_until(&g_syncB, NPART); }
    __syncthreads();
    __threadfence();

    // ---------------- phase 2: merge softmax partials, ctx from L2-hot enc ----------
    {
        float m = g_spart[2 * tid], s = g_spart[2 * tid + 1];
        const float m2 = g_spart[2 * (tid + 256)], s2 = g_spart[2 * (tid + 256) + 1];
        const float nm0 = fmaxf(m, m2);
        s = s * __expf(m - nm0) + s2 * __expf(m2 - nm0);
        m = nm0;
#pragma unroll
        for (int o = 16; o > 0; o >>= 1) {
            const float om = __shfl_down_sync(0xFFFFFFFFu, m, o);
            const float os = __shfl_down_sync(0xFFFFFFFFu, s, o);
            const float nm = fmaxf(m, om);
            s = s * __expf(m - nm) + os * __expf(om - nm);
            m = nm;
        }
        if (lane == 0) { red[0][warp] = m; red[1][warp] = s; }
    }
    __syncthreads();
    if (tid < 8) {
        float M = red[0][0], S = red[1][0];
#pragma unroll
        for (int k = 1; k < 8; k++) {
            const float nm = fmaxf(M, red[0][k]);
            S = S * __expf(M - nm) + red[1][k] * __expf(red[0][k] - nm);
            M = nm;
        }
        wts[tid] = __expf(sarr[tid] - M) / S;
    }
    __syncthreads();
    {
        float4 acc = make_float4(0.f, 0.f, 0.f, 0.f);
#pragma unroll
        for (int l = 0; l < 8; l++) {
            const float w = wts[l];
            const float4 v = e4[(size_t)(l0 + l) * 256 + tid];   // L2 hit
            acc.x += w * v.x; acc.y += w * v.y;
            acc.z += w * v.z; acc.w += w * v.w;
        }
        g_ctx_part4[b * 256 + tid] = acc;
    }
    __threadfence();
    __syncthreads();
    if (tid == 0) atomicAdd(&g_syncC, 1);

    // ---------------- phase 3: blocks 0..63 reduce the L2-hot partials ----------------
    if (b < NRED) {
        if (tid == 0) spin_until(&g_syncC, NPART);
        __syncthreads();
        __threadfence();
        __shared__ float4 sred[256];
        const int c4 = tid & 3;
        const int pg = tid >> 2;
        float4 racc = make_float4(0.f, 0.f, 0.f, 0.f);
#pragma unroll
        for (int k = 0; k < NPART / 64; k++) {
            const float4 v = g_ctx_part4[(pg + 64 * k) * 256 + b * 4 + c4];
            racc.x += v.x; racc.y += v.y; racc.z += v.z; racc.w += v.w;
        }
        sred[tid] = racc;
        __syncthreads();
#pragma unroll
        for (int off = 32; off >= 1; off >>= 1) {
            if (pg < off) {
                const float4 v = sred[tid + off * 4];
                float4 t = sred[tid];
                t.x += v.x; t.y += v.y; t.z += v.z; t.w += v.w;
                sred[tid] = t;
            }
            __syncthreads();
        }
        if (pg == 0) ((float4*)g_concat)[b * 4 + c4] = sred[tid];
    }
}

// ============ 2) logits: 2 rows per warp (32 rows/block) for doubled MLP ============
__global__ void __launch_bounds__(512) logits_kernel(
    const float* __restrict__ out_w, const float* __restrict__ out_b,
    float* __restrict__ logits)
{
    __shared__ float4 cs[512];          // concat (2048 floats) as float4
    const int tid = threadIdx.x;
    const float4* cc = (const float4*)g_concat;
    cs[tid] = cc[tid];
    __syncthreads();
    const int warp = tid >> 5, lane = tid & 31;
    const int r0 = blockIdx.x * 32 + warp * 2;       // warp covers rows r0, r0+1
    const float4* w0 = (const float4*)(out_w + (size_t)r0 * (2 * H));
    const float4* w1 = w0 + 512;                     // next row (2048 floats = 512 float4)
    float acc0 = 0.f, acc1 = 0.f;
    if (r0 + 1 < V) {
#pragma unroll
        for (int i = 0; i < 16; i++) {
            const float4 c4 = cs[lane + 32 * i];
            const float4 a4 = __ldcs(&w0[lane + 32 * i]);
            const float4 b4 = __ldcs(&w1[lane + 32 * i]);
            acc0 += a4.x * c4.x + a4.y * c4.y + a4.z * c4.z + a4.w * c4.w;
            acc1 += b4.x * c4.x + b4.y * c4.y + b4.z * c4.z + b4.w * c4.w;
        }
        acc0 = warp_sum(acc0);
        acc1 = warp_sum(acc1);
        if (lane == 0) {
            logits[r0]     = acc0 + out_b[r0];
            logits[r0 + 1] = acc1 + out_b[r0 + 1];
        }
    } else if (r0 < V) {
#pragma unroll
        for (int i = 0; i < 16; i++) {
            const float4 c4 = cs[lane + 32 * i];
            const float4 a4 = __ldcs(&w0[lane + 32 * i]);
            acc0 += a4.x * c4.x + a4.y * c4.y + a4.z * c4.z + a4.w * c4.w;
        }
        acc0 = warp_sum(acc0);
        if (lane == 0) logits[r0] = acc0 + out_b[r0];
    }
}

// ============ 3) finalize: per-block LSE partial + spin + redundant merge + subtract ====
__global__ void __launch_bounds__(256) finalize_kernel(float* __restrict__ logits)
{
    __shared__ float sm[8], ss[8];
    __shared__ float lse_s;
    const int tid = threadIdx.x;
    const int warp = tid >> 5, lane = tid & 31;
    const int v = blockIdx.x * 256 + tid;
    const float lg = (v < V) ? logits[v] : NEG_BIG;

    if (blockIdx.x == 0 && tid == 0) { g_syncA = 0; g_syncB = 0; g_syncC = 0; }  // reset for next replay

    // block-local (max, sumexp)
    float m = lg;
#pragma unroll
    for (int o = 16; o > 0; o >>= 1) m = fmaxf(m, __shfl_down_sync(0xFFFFFFFFu, m, o));
    if (lane == 0) sm[warp] = m;
    __syncthreads();
    if (tid == 0) {
        float t = sm[0];
#pragma unroll
        for (int k = 1; k < 8; k++) t = fmaxf(t, sm[k]);
        lse_s = t;   // broadcast of block max
    }
    __syncthreads();
    const float bm = lse_s;
    float s = (v < V) ? __expf(lg - bm) : 0.f;
    s = warp_sum(s);
    if (lane == 0) ss[warp] = s;
    __syncthreads();
    if (tid == 0) {
        float t = ss[0];
#pragma unroll
        for (int k = 1; k < 8; k++) t += ss[k];
        g_part[2 * blockIdx.x]     = bm;
        g_part[2 * blockIdx.x + 1] = t;
        __threadfence();
        atomicAdd(&g_lse_done, 1);
        while (atomicAdd(&g_lse_done, 0) < FIN_BLOCKS) { }
    }
    __syncthreads();
    __threadfence();

    // redundant merge of all 197 pairs (L2-hot, fixed order -> deterministic)
    float mm = NEG_BIG, msum = 0.f;
    if (tid < FIN_BLOCKS) { mm = g_part[2 * tid]; msum = g_part[2 * tid + 1]; }
#pragma unroll
    for (int o = 16; o > 0; o >>= 1) {
        const float om = __shfl_down_sync(0xFFFFFFFFu, mm, o);
        const float os = __shfl_down_sync(0xFFFFFFFFu, msum, o);
        const float nm = fmaxf(mm, om);
        msum = msum * __expf(mm - nm) + os * __expf(om - nm);
        mm = nm;
    }
    if (lane == 0) { sm[warp] = mm; ss[warp] = msum; }
    __syncthreads();
    if (tid == 0) {
        float M = sm[0], S = ss[0];
#pragma unroll
        for (int k = 1; k < 8; k++) {
            const float nm = fmaxf(M, sm[k]);
            S = S * __expf(M - nm) + ss[k] * __expf(sm[k] - nm);
            M = nm;
        }
        lse_s = M + logf(S);
    }
    __syncthreads();
    if (v < V) logits[v] = lg - lse_s;
}

// ---------------- launcher ----------------
extern "C" void kernel_launch(void* const* d_in, const int* in_sizes, int n_in,
                              void* d_out, int out_size)
{
    const int*   inp   = (const int*)  d_in[0];   // token id (read low 32 bits)
    const float* hidden= (const float*)d_in[1];
    const float* enc   = (const float*)d_in[2];
    const float* emb   = (const float*)d_in[3];
    const float* w_ih  = (const float*)d_in[4];
    const float* w_hh  = (const float*)d_in[5];
    const float* b_ih  = (const float*)d_in[6];
    const float* b_hh  = (const float*)d_in[7];
    const float* out_w = (const float*)d_in[8];
    const float* out_b = (const float*)d_in[9];
    float* out = (float*)d_out;                   // [0..V) log-probs, [V..V+H) h_new

    fused_attn_kernel<<<NPART, 256>>>(inp, hidden, emb, w_ih, w_hh, b_ih, b_hh,
                                      enc, out + V);
    logits_kernel<<<(V + 31) / 32, 512>>>(out_w, out_b, out);
    finalize_kernel<<<FIN_BLOCKS, 256>>>(out);
}

// round 11
// speedup vs baseline: 1.1540x; 1.1540x over previous
#include <cuda_runtime.h>
#include <math.h>

#define H 1024
#define V 50257
#define L 4096
#define NPART 512                   // ctx_part blocks (8 enc rows each)
#define NRED 64                     // reducer blocks inside ctx_part
#define FIN_BLOCKS ((V + 255) / 256)   // 197
#define NEG_BIG (-3.0e38f)

// ---------------- device scratch (no allocations allowed) ----------------
__device__ float g_concat[2 * H];            // [0..H) = ctx, [H..2H) = h_new
__device__ float4 g_ctx_part4[NPART * 256];  // 512 partials x 1024 cols (float4) = 2 MB
__device__ float g_scores[L];
__device__ float g_spart[2 * NPART];         // per-block (max, sumexp) for attn softmax
__device__ float g_part[2 * FIN_BLOCKS];     // per-block (max, sumexp) for logit LSE
__device__ int   g_ctx_done;
__device__ int   g_lse_done;

// ---------------- helpers ----------------
__device__ __forceinline__ float warp_sum(float v) {
#pragma unroll
    for (int o = 16; o > 0; o >>= 1) v += __shfl_down_sync(0xFFFFFFFFu, v, o);
    return v;
}
__device__ __forceinline__ float dot4(const float4 a, const float4 b) {
    return a.x * b.x + a.y * b.y + a.z * b.z + a.w * b.w;
}

// ---------------- 1) GRU cell: one block per output element j ----------------
__global__ void __launch_bounds__(128) gru_kernel(
    const int* __restrict__ inp, const float* __restrict__ hidden,
    const float* __restrict__ embedding,
    const float* __restrict__ w_ih, const float* __restrict__ w_hh,
    const float* __restrict__ b_ih, const float* __restrict__ b_hh,
    float* __restrict__ out_h)
{
    __shared__ float4 xs[H / 4];
    __shared__ float4 hs[H / 4];
    __shared__ float red[6][4];
    const int j = blockIdx.x;
    const int tid = threadIdx.x;
    const int idx = inp[0];   // low 32 bits of the (int64) token id — LE safe

    if (j == 0 && tid == 0) { g_ctx_done = 0; g_lse_done = 0; }   // reset fusion counters

    const float4* emb4 = (const float4*)(embedding + (size_t)idx * H);
    const float4* hid4 = (const float4*)hidden;
    xs[tid]       = emb4[tid];        xs[tid + 128] = emb4[tid + 128];
    hs[tid]       = hid4[tid];        hs[tid + 128] = hid4[tid + 128];
    __syncthreads();

    const float4* wi0 = (const float4*)(w_ih + (size_t)j * H);
    const float4* wi1 = (const float4*)(w_ih + (size_t)(j + H) * H);
    const float4* wi2 = (const float4*)(w_ih + (size_t)(j + 2 * H) * H);
    const float4* wh0 = (const float4*)(w_hh + (size_t)j * H);
    const float4* wh1 = (const float4*)(w_hh + (size_t)(j + H) * H);
    const float4* wh2 = (const float4*)(w_hh + (size_t)(j + 2 * H) * H);

    float a0 = 0.f, a1 = 0.f, a2 = 0.f, a3 = 0.f, a4 = 0.f, a5 = 0.f;
#pragma unroll
    for (int p = 0; p < 2; p++) {
        const int k = tid + 128 * p;
        const float4 xv = xs[k], hv = hs[k];
        float4 w;
        w = wi0[k]; a0 += dot4(w, xv);
        w = wi1[k]; a1 += dot4(w, xv);
        w = wi2[k]; a2 += dot4(w, xv);
        w = wh0[k]; a3 += dot4(w, hv);
        w = wh1[k]; a4 += dot4(w, hv);
        w = wh2[k]; a5 += dot4(w, hv);
    }
#if __CUDA_ARCH__ >= 900
    cudaTriggerProgrammaticLaunchCompletion();   // let scores' blocks launch + prefetch enc
#endif
    a0 = warp_sum(a0); a1 = warp_sum(a1); a2 = warp_sum(a2);
    a3 = warp_sum(a3); a4 = warp_sum(a4); a5 = warp_sum(a5);
    const int warp = tid >> 5, lane = tid & 31;
    if (lane == 0) {
        red[0][warp] = a0; red[1][warp] = a1; red[2][warp] = a2;
        red[3][warp] = a3; red[4][warp] = a4; red[5][warp] = a5;
    }
    __syncthreads();
    if (tid == 0) {
        float s[6];
#pragma unroll
        for (int q = 0; q < 6; q++) s[q] = red[q][0] + red[q][1] + red[q][2] + red[q][3];
        const float i_r = s[0] + b_ih[j];
        const float i_z = s[1] + b_ih[j + H];
        const float i_n = s[2] + b_ih[j + 2 * H];
        const float h_r = s[3] + b_hh[j];
        const float h_z = s[4] + b_hh[j + H];
        const float h_n = s[5] + b_hh[j + 2 * H];
        const float r = 1.f / (1.f + __expf(-(i_r + h_r)));
        const float z = 1.f / (1.f + __expf(-(i_z + h_z)));
        const float n = tanhf(i_n + r * h_n);
        const float hj = ((const float*)hs)[j];
        const float hv = (1.f - z) * n + z * hj;
        g_concat[H + j] = hv;     // h_new half of concat
        out_h[j]        = hv;     // second output tensor
    }
}

// ---------------- 2) scores: prefetch enc into regs BEFORE the dependency wait --------
__global__ void __launch_bounds__(256) scores_kernel(const float* __restrict__ enc)
{
    __shared__ float4 hshr[H / 4];
    __shared__ float sarr[8];
    const int tid = threadIdx.x;
    const int warp = tid >> 5, lane = tid & 31;
    const int row = blockIdx.x * 8 + warp;      // grid = L/8 = 512
    const float4* er = (const float4*)(enc + (size_t)row * H);
    float4 rv[8];
#pragma unroll
    for (int i = 0; i < 8; i++) rv[i] = er[lane + 32 * i];   // independent of gru
#if __CUDA_ARCH__ >= 900
    cudaGridDependencySynchronize();             // wait for gru before touching h_new
#endif
    const float4* hc = (const float4*)(&g_concat[H]);
    hshr[tid] = hc[tid];
    __syncthreads();
    float acc = 0.f;
#pragma unroll
    for (int i = 0; i < 8; i++) acc += dot4(rv[i], hshr[lane + 32 * i]);
    acc = warp_sum(acc);
    if (lane == 0) { g_scores[row] = acc; sarr[warp] = acc; }
    __syncthreads();
    if (tid == 0) {
        float m = sarr[0];
#pragma unroll
        for (int k = 1; k < 8; k++) m = fmaxf(m, sarr[k]);
        float s = 0.f;
#pragma unroll
        for (int k = 0; k < 8; k++) s += __expf(sarr[k] - m);
        g_spart[2 * blockIdx.x]     = m;
        g_spart[2 * blockIdx.x + 1] = s;
    }
}

// ---- 3) ctx: partials + FUSED reduction (blocks 0..63 spin, all blocks co-resident) ----
__global__ void __launch_bounds__(256) ctx_part_kernel(const float* __restrict__ enc)
{
    __shared__ float sm[8], ss[8];
    __shared__ float wts[8];
    const int tid = threadIdx.x;
    const int warp = tid >> 5, lane = tid & 31;
    const int l0 = blockIdx.x * 8;           // grid = NPART = 512
#if __CUDA_ARCH__ >= 900
    cudaGridDependencySynchronize();         // wait for scores
#endif

    // ---- merge the 512 (max,sumexp) pairs: 2 per thread, then tree ----
    float m = g_spart[2 * tid], s = g_spart[2 * tid + 1];
    {
        const float m2 = g_spart[2 * (tid + 256)], s2 = g_spart[2 * (tid + 256) + 1];
        const float nm = fmaxf(m, m2);
        s = s * __expf(m - nm) + s2 * __expf(m2 - nm);
        m = nm;
    }
#pragma unroll
    for (int o = 16; o > 0; o >>= 1) {
        const float om = __shfl_down_sync(0xFFFFFFFFu, m, o);
        const float os = __shfl_down_sync(0xFFFFFFFFu, s, o);
        const float nm = fmaxf(m, om);
        s = s * __expf(m - nm) + os * __expf(om - nm);
        m = nm;
    }
    if (lane == 0) { sm[warp] = m; ss[warp] = s; }
    __syncthreads();
    if (tid < 8) {
        float M = sm[0], S = ss[0];
#pragma unroll
        for (int k = 1; k < 8; k++) {
            const float nm = fmaxf(M, sm[k]);
            S = S * __expf(M - nm) + ss[k] * __expf(sm[k] - nm);
            M = nm;
        }
        wts[tid] = __expf(g_scores[l0 + tid] - M) / S;   // this block's 8 attn weights
    }
    __syncthreads();

    // ---- weighted row accumulation: 8 independent float4 loads (enc L2-hot) ----
    const float4* e4 = (const float4*)enc;
    float4 acc = make_float4(0.f, 0.f, 0.f, 0.f);
#pragma unroll
    for (int l = 0; l < 8; l++) {
        const float a = wts[l];
        const float4 v = e4[(size_t)(l0 + l) * 256 + tid];
        acc.x += a * v.x; acc.y += a * v.y; acc.z += a * v.z; acc.w += a * v.w;
    }
    g_ctx_part4[blockIdx.x * 256 + tid] = acc;
    __threadfence();
    __syncthreads();
    if (tid == 0) atomicAdd(&g_ctx_done, 1);

    // ---- blocks 0..63: wait for all partials, then reduce ----
    if (blockIdx.x < NRED) {
        if (tid == 0) { while (atomicAdd(&g_ctx_done, 0) < NPART) { } }
        __syncthreads();
        __threadfence();
        __shared__ float4 sred[256];
        const int b  = blockIdx.x;
        const int c4 = tid & 3;
        const int pg = tid >> 2;
        float4 racc = make_float4(0.f, 0.f, 0.f, 0.f);
#pragma unroll
        for (int k = 0; k < NPART / 64; k++) {
            const float4 v = g_ctx_part4[(pg + 64 * k) * 256 + b * 4 + c4];
            racc.x += v.x; racc.y += v.y; racc.z += v.z; racc.w += v.w;
        }
        sred[tid] = racc;
        __syncthreads();
#pragma unroll
        for (int off = 32; off >= 1; off >>= 1) {
            if (pg < off) {
                const float4 v = sred[tid + off * 4];
                float4 t = sred[tid];
                t.x += v.x; t.y += v.y; t.z += v.z; t.w += v.w;
                sred[tid] = t;
            }
            __syncthreads();
        }
        if (pg == 0) ((float4*)g_concat)[b * 4 + c4] = sred[tid];
    }
}

// ---------------- 4) logits: warp-per-row float4 matvec (R7 shape, 83.9% DRAM) --------
__global__ void __launch_bounds__(512) logits_kernel(
    const float* __restrict__ out_w, const float* __restrict__ out_b,
    float* __restrict__ logits)
{
    __shared__ float4 cs[512];          // concat (2048 floats) as float4
    const int tid = threadIdx.x;
#if __CUDA_ARCH__ >= 900
    cudaGridDependencySynchronize();    // wait for ctx_part
#endif
    const float4* cc = (const float4*)g_concat;
    cs[tid] = cc[tid];
    __syncthreads();
    const int warp = tid >> 5, lane = tid & 31;
    const int row = blockIdx.x * 16 + warp;
    if (row >= V) return;
    const float4* wr = (const float4*)(out_w + (size_t)row * (2 * H));
    float acc = 0.f;
#pragma unroll
    for (int i = 0; i < 16; i++) {
        const float4 w4 = __ldcs(&wr[lane + 32 * i]);   // streaming: don't pollute L2
        const float4 c4 = cs[lane + 32 * i];
        acc += w4.x * c4.x + w4.y * c4.y + w4.z * c4.z + w4.w * c4.w;
    }
    acc = warp_sum(acc);
    if (lane == 0) logits[row] = acc + out_b[row];
}

// ---- 5) finalize: per-block LSE partial + spin + redundant merge + subtract ----
__global__ void __launch_bounds__(256) finalize_kernel(float* __restrict__ logits)
{
    __shared__ float sm[8], ss[8];
    __shared__ float lse_s;
    const int tid = threadIdx.x;
    const int warp = tid >> 5, lane = tid & 31;
    const int v = blockIdx.x * 256 + tid;
#if __CUDA_ARCH__ >= 900
    cudaGridDependencySynchronize();    // wait for logits
#endif
    const float lg = (v < V) ? logits[v] : NEG_BIG;

    // block-local (max, sumexp)
    float m = lg;
#pragma unroll
    for (int o = 16; o > 0; o >>= 1) m = fmaxf(m, __shfl_down_sync(0xFFFFFFFFu, m, o));
    if (lane == 0) sm[warp] = m;
    __syncthreads();
    if (tid == 0) {
        float t = sm[0];
#pragma unroll
        for (int k = 1; k < 8; k++) t = fmaxf(t, sm[k]);
        lse_s = t;   // broadcast of block max
    }
    __syncthreads();
    const float bm = lse_s;
    float s = (v < V) ? __expf(lg - bm) : 0.f;
    s = warp_sum(s);
    if (lane == 0) ss[warp] = s;
    __syncthreads();
    if (tid == 0) {
        float t = ss[0];
#pragma unroll
        for (int k = 1; k < 8; k++) t += ss[k];
        g_part[2 * blockIdx.x]     = bm;
        g_part[2 * blockIdx.x + 1] = t;
        __threadfence();
        atomicAdd(&g_lse_done, 1);
        while (atomicAdd(&g_lse_done, 0) < FIN_BLOCKS) { }
    }
    __syncthreads();
    __threadfence();

    // redundant merge of all 197 pairs (L2-hot, fixed order -> deterministic)
    float mm = NEG_BIG, msum = 0.f;
    if (tid < FIN_BLOCKS) { mm = g_part[2 * tid]; msum = g_part[2 * tid + 1]; }
#pragma unroll
    for (int o = 16; o > 0; o >>= 1) {
        const float om = __shfl_down_sync(0xFFFFFFFFu, mm, o);
        const float os = __shfl_down_sync(0xFFFFFFFFu, msum, o);
        const float nm = fmaxf(mm, om);
        msum = msum * __expf(mm - nm) + os * __expf(om - nm);
        mm = nm;
    }
    if (lane == 0) { sm[warp] = mm; ss[warp] = msum; }
    __syncthreads();
    if (tid == 0) {
        float M = sm[0], S = ss[0];
#pragma unroll
        for (int k = 1; k < 8; k++) {
            const float nm = fmaxf(M, sm[k]);
            S = S * __expf(M - nm) + ss[k] * __expf(sm[k] - nm);
            M = nm;
        }
        lse_s = M + logf(S);
    }
    __syncthreads();
    if (v < V) logits[v] = lg - lse_s;
}

// ---------------- launcher (PDL on the 4 dependent edges) ----------------
static void launch_pdl(void* fn, dim3 grid, dim3 block, void** args)
{
    cudaLaunchConfig_t cfg = {};
    cfg.gridDim = grid;
    cfg.blockDim = block;
    cudaLaunchAttribute attr[1];
    attr[0].id = cudaLaunchAttributeProgrammaticStreamSerialization;
    attr[0].val.programmaticStreamSerializationAllowed = 1;
    cfg.attrs = attr;
    cfg.numAttrs = 1;
    cudaLaunchKernelExC(&cfg, fn, args);
}

extern "C" void kernel_launch(void* const* d_in, const int* in_sizes, int n_in,
                              void* d_out, int out_size)
{
    const int*   inp   = (const int*)  d_in[0];   // token id (read low 32 bits)
    const float* hidden= (const float*)d_in[1];
    const float* enc   = (const float*)d_in[2];
    const float* emb   = (const float*)d_in[3];
    const float* w_ih  = (const float*)d_in[4];
    const float* w_hh  = (const float*)d_in[5];
    const float* b_ih  = (const float*)d_in[6];
    const float* b_hh  = (const float*)d_in[7];
    const float* out_w = (const float*)d_in[8];
    const float* out_b = (const float*)d_in[9];
    float* out = (float*)d_out;                   // [0..V) log-probs, [V..V+H) h_new
    float* out_h = out + V;

    gru_kernel<<<H, 128>>>(inp, hidden, emb, w_ih, w_hh, b_ih, b_hh, out_h);

    {   // scores (PDL: launches during gru tail, prefetches enc)
        void* args[] = { (void*)&enc };
        launch_pdl((void*)scores_kernel, dim3(L / 8), dim3(256), args);
    }
    {   // ctx_part (PDL)
        void* args[] = { (void*)&enc };
        launch_pdl((void*)ctx_part_kernel, dim3(NPART), dim3(256), args);
    }
    {   // logits (PDL)
        void* args[] = { (void*)&out_w, (void*)&out_b, (void*)&out };
        launch_pdl((void*)logits_kernel, dim3((V + 15) / 16), dim3(512), args);
    }
    {   // finalize (PDL)
        void* args[] = { (void*)&out };
        launch_pdl((void*)finalize_kernel, dim3(FIN_BLOCKS), dim3(256), args);
    }
}